// round 13
// baseline (speedup 1.0000x reference)
#include <cuda_runtime.h>
#include <cuda_bf16.h>
#include <math.h>
#include <stdint.h>

// Problem dims (fixed)
#define B_  64
#define T_  512
#define E_  256
#define H_  256
#define O_  256
#define M_  (T_ * B_)          // 32768 rows

typedef unsigned long long u64;
typedef unsigned int u32;

// ---------------------------------------------------------------------------
// scan config (R8 winner)
// ---------------------------------------------------------------------------
#define KREGP 100
#define KSH2  14
#define SMEM_SCAN ((2 * H_) * sizeof(float) + (KSH2 * H_) * sizeof(ulonglong2))
#define XPF 4

__device__ __forceinline__ u64 pk2(float lo, float hi) {
    u64 r;
    asm("mov.b64 %0, {%1, %2};" : "=l"(r) : "f"(lo), "f"(hi));
    return r;
}
__device__ __forceinline__ void upk2(u64 v, float& lo, float& hi) {
    asm("mov.b64 {%0, %1}, %2;" : "=f"(lo), "=f"(hi) : "l"(v));
}
#define FMA2(d, a, b, c) \
    asm("fma.rn.f32x2 %0, %1, %2, %3;" : "=l"(d) : "l"(a), "l"(b), "l"(c))

__device__ __forceinline__ float fast_tanh(float v) {
    float x = fminf(fmaxf(v, -15.f), 15.f);
    float e = __expf(2.f * x);
    return __fdividef(e - 1.f, e + 1.f);
}

// ---------------------------------------------------------------------------
// warp-mma + cp.async helpers
// ---------------------------------------------------------------------------
__device__ __forceinline__ u32 smem_u32(const void* p) {
    u32 a;
    asm("{ .reg .u64 t; cvta.to.shared.u64 t, %1; cvt.u32.u64 %0, t; }" : "=r"(a) : "l"(p));
    return a;
}
#define LDSM_X4(r, addr) \
    asm volatile("ldmatrix.sync.aligned.m8n8.x4.shared.b16 {%0,%1,%2,%3}, [%4];" \
        : "=r"((r)[0]), "=r"((r)[1]), "=r"((r)[2]), "=r"((r)[3]) : "r"(addr))
#define MMA_BF16(c, a, b0, b1) \
    asm volatile("mma.sync.aligned.m16n8k16.row.col.f32.bf16.bf16.f32 " \
        "{%0,%1,%2,%3}, {%4,%5,%6,%7}, {%8,%9}, {%0,%1,%2,%3};" \
        : "+f"((c)[0]), "+f"((c)[1]), "+f"((c)[2]), "+f"((c)[3]) \
        : "r"((a)[0]), "r"((a)[1]), "r"((a)[2]), "r"((a)[3]), "r"(b0), "r"(b1))
#define CP16(dst, src) \
    asm volatile("cp.async.cg.shared.global [%0], [%1], 16;" :: "r"(dst), "l"(src))
#define CP_COMMIT()  asm volatile("cp.async.commit_group;" ::: "memory")
#define CP_WAIT1()   asm volatile("cp.async.wait_group 1;" ::: "memory")
#define CP_WAIT0()   asm volatile("cp.async.wait_group 0;" ::: "memory")

// ---------------------------------------------------------------------------
// Static device scratch
// ---------------------------------------------------------------------------
__device__ float g_xf[(size_t)T_ * B_ * H_];
__device__ float g_xb[(size_t)T_ * B_ * H_];

// X pre-converted to bf16 hi/lo (same [b][t][e] layout)
__device__ __nv_bfloat16 g_Xh[(size_t)B_ * T_ * E_];
__device__ __nv_bfloat16 g_Xl[(size_t)B_ * T_ * E_];
// h history as bf16 hi/lo: [m][k], m = t*64+b, k<512 (fwd cols 0..255, bwd 256..511)
__device__ __nv_bfloat16 g_hh[(size_t)M_ * (2 * H_)];
__device__ __nv_bfloat16 g_hl[(size_t)M_ * (2 * H_)];

// weights pre-split bf16 hi/lo, TRANSPOSED to [n][k] (k contiguous)
__device__ __nv_bfloat16 g_pBh[2 * H_ * E_];
__device__ __nv_bfloat16 g_pBl[2 * H_ * E_];
__device__ __nv_bfloat16 g_oBh[O_ * 2 * H_];
__device__ __nv_bfloat16 g_oBl[O_ * 2 * H_];

// ---------------------------------------------------------------------------
// GEMM smem: A (hi/lo) and B (hi/lo), BOTH double-buffered, all cp.async.
// rows padded to 144B -> LDSM conflict-free. 108KB/CTA -> 2 CTAs/SM.
// ---------------------------------------------------------------------------
#define ROWB 144
#define ABUF 36864           // per stage: AH at +0 (18432), AL at +18432
#define SM_B0 (2 * ABUF)     // 73728
#define BBUF  18432          // per stage: BH at +0 (9216), BL at +9216
#define SMEM_TC (SM_B0 + 2 * BBUF)   // 110592

// ---------------------------------------------------------------------------
// setup: split + transpose weights
// ---------------------------------------------------------------------------
__global__ void setup_kernel(const float* __restrict__ Wf,
                             const float* __restrict__ Wb,
                             const float* __restrict__ Why)
{
    const int stride = gridDim.x * blockDim.x;
    for (int e = blockIdx.x * blockDim.x + threadIdx.x; e < E_ * H_; e += stride) {
        int k = e >> 8, n = e & 255;
        int idx = n * E_ + k;
        float wf = Wf[e], wb = Wb[e];
        __nv_bfloat16 hf = __float2bfloat16_rn(wf);
        __nv_bfloat16 hb = __float2bfloat16_rn(wb);
        g_pBh[idx] = hf;
        g_pBl[idx] = __float2bfloat16_rn(wf - __bfloat162float(hf));
        g_pBh[H_ * E_ + idx] = hb;
        g_pBl[H_ * E_ + idx] = __float2bfloat16_rn(wb - __bfloat162float(hb));
    }
    for (int e = blockIdx.x * blockDim.x + threadIdx.x; e < 2 * H_ * O_; e += stride) {
        int k = e >> 8, n = e & 255;
        int idx = n * (2 * H_) + k;
        float w = Why[e];
        __nv_bfloat16 h = __float2bfloat16_rn(w);
        g_oBh[idx] = h;
        g_oBl[idx] = __float2bfloat16_rn(w - __bfloat162float(h));
    }
}

// convert X fp32 -> bf16 hi/lo (HBM-bound, ~11us)
__global__ void xcvt_kernel(const float* __restrict__ X)
{
    const size_t N = (size_t)B_ * T_ * E_;
    const size_t stride = (size_t)gridDim.x * blockDim.x;
    for (size_t i = (size_t)blockIdx.x * blockDim.x + threadIdx.x; i < N; i += stride) {
        float v = X[i];
        __nv_bfloat16 h = __float2bfloat16_rn(v);
        g_Xh[i] = h;
        g_Xl[i] = __float2bfloat16_rn(v - __bfloat162float(h));
    }
}

// ---------------------------------------------------------------------------
// split-bf16 warp-MMA GEMM body: 128(M) x 64(N) tile, K = NKT*64.
// A and B both streamed by cp.async (pre-converted bf16 hi/lo in global).
// 8 warps as 4(M) x 2(N); warp tile 32x32.
// ---------------------------------------------------------------------------
template <int NKT, int MODE>
__device__ __forceinline__ void gemm_mma_body(
    const __nv_bfloat16* __restrict__ Ah,
    const __nv_bfloat16* __restrict__ Al,
    const __nv_bfloat16* __restrict__ Bh,
    const __nv_bfloat16* __restrict__ Bl,
    const float* __restrict__ bias,
    float* __restrict__ Cdst,
    int m0, int n0, int dir)
{
    extern __shared__ char smem[];
    const u32 smb = smem_u32(smem);
    const int tid = threadIdx.x;
    const int wid = tid >> 5;
    const int l   = tid & 31;
    const int wm  = wid & 3;       // 4 warp-rows of 32
    const int wn  = wid >> 2;      // 2 warp-cols of 32
    const int K   = NKT * 64;

    // A loader: row r, k-half hf; 4 cp16 hi + 4 cp16 lo per slab
    const int r  = tid >> 1;
    const int hf = tid & 1;
    size_t aoff;
    {
        const int m = m0 + r;
        if (MODE == 0) {
            int t = m >> 6, b = m & 63;
            int xt = dir ? (T_ - 1 - t) : t;
            aoff = ((size_t)b * T_ + xt) * E_ + hf * 32;
        } else {
            aoff = (size_t)m * (2 * H_) + hf * 32;
        }
    }
    const u32 adst_off = (u32)(r * ROWB + hf * 64);

    // B loader: slot = (arr, row), 2 threads per slot (64B halves)
    const int slot  = tid >> 1;
    const int bhalf = tid & 1;
    const int barr  = slot >> 6;
    const int rb    = slot & 63;
    const __nv_bfloat16* bsrc = (barr ? Bl : Bh) + (size_t)(n0 + rb) * K + bhalf * 32;
    const u32 bdst_off = (u32)(SM_B0 + barr * 9216 + rb * ROWB + bhalf * 64);

    // LDSM per-lane offsets (stage base added at use)
    u32 aOff[2];
#pragma unroll
    for (int f = 0; f < 2; f++)
        aOff[f] = (u32)((wm * 32 + 16 * f + (l & 15)) * ROWB + (l >> 4) * 16);
    u32 bOff[2];
#pragma unroll
    for (int p = 0; p < 2; p++)
        bOff[p] = (u32)((wn * 32 + 16 * p + (l & 7) + (l >> 4) * 8) * ROWB + ((l >> 3) & 1) * 16);

    float cc[2][4][4];
#pragma unroll
    for (int f = 0; f < 2; f++)
#pragma unroll
        for (int g = 0; g < 4; g++)
#pragma unroll
            for (int i = 0; i < 4; i++) cc[f][g][i] = 0.f;

    // ---- prologue: stage 0 for kt = 0 ----
#pragma unroll
    for (int i = 0; i < 4; i++) {
        CP16(smb + adst_off + i * 16,          (const char*)(Ah + aoff) + i * 16);
        CP16(smb + 18432 + adst_off + i * 16,  (const char*)(Al + aoff) + i * 16);
        CP16(smb + bdst_off + i * 16,          (const char*)(bsrc) + i * 16);
    }
    CP_COMMIT();

    for (int kt = 0; kt < NKT; kt++) {
        const int buf = kt & 1;

        if (kt > 0) __syncthreads();   // all MMA(kt-1) done -> other stage free

        if (kt + 1 < NKT) {
            const int nb = 1 - buf;
            const char* ah = (const char*)(Ah + aoff + (kt + 1) * 64);
            const char* al = (const char*)(Al + aoff + (kt + 1) * 64);
            const char* bs = (const char*)(bsrc + (kt + 1) * 64);
#pragma unroll
            for (int i = 0; i < 4; i++) {
                CP16(smb + nb * ABUF + adst_off + i * 16,          ah + i * 16);
                CP16(smb + nb * ABUF + 18432 + adst_off + i * 16,  al + i * 16);
                CP16(smb + bdst_off + nb * BBUF + i * 16,          bs + i * 16);
            }
            CP_COMMIT();
            CP_WAIT1();                // stage kt landed
        } else {
            CP_WAIT0();
        }
        __syncthreads();               // stage kt visible to all

        const u32 ab = smb + buf * ABUF;
        const u32 bb = smb + buf * BBUF;
#pragma unroll
        for (int ks = 0; ks < 4; ks++) {
            const u32 kb = ks * 32;
            u32 ah2[2][4], al2[2][4], bh2[2][4], bl2[2][4];
#pragma unroll
            for (int f = 0; f < 2; f++) {
                LDSM_X4(ah2[f], ab + aOff[f] + kb);
                LDSM_X4(al2[f], ab + 18432 + aOff[f] + kb);
            }
#pragma unroll
            for (int p = 0; p < 2; p++) {
                LDSM_X4(bh2[p], bb + SM_B0 + bOff[p] + kb);
                LDSM_X4(bl2[p], bb + SM_B0 + 9216 + bOff[p] + kb);
            }
#pragma unroll
            for (int f = 0; f < 2; f++)
#pragma unroll
                for (int g = 0; g < 4; g++) {
                    u32 h0 = bh2[g >> 1][(g & 1) * 2], h1 = bh2[g >> 1][(g & 1) * 2 + 1];
                    u32 l0 = bl2[g >> 1][(g & 1) * 2], l1 = bl2[g >> 1][(g & 1) * 2 + 1];
                    MMA_BF16(cc[f][g], ah2[f], h0, h1);
                    MMA_BF16(cc[f][g], ah2[f], l0, l1);
                    MMA_BF16(cc[f][g], al2[f], h0, h1);
                }
        }
    }

    // epilogue
#pragma unroll
    for (int f = 0; f < 2; f++) {
        const int row0 = m0 + wm * 32 + 16 * f + (l >> 2);
#pragma unroll
        for (int g = 0; g < 4; g++) {
            const int col = n0 + wn * 32 + 8 * g + (l & 3) * 2;
            float2 bv = *(const float2*)(bias + col);
            float2 v0 = { cc[f][g][0] + bv.x, cc[f][g][1] + bv.y };
            float2 v1 = { cc[f][g][2] + bv.x, cc[f][g][3] + bv.y };
            if (MODE == 0) {
                *(float2*)(Cdst + (size_t)row0 * H_ + col) = v0;
                *(float2*)(Cdst + (size_t)(row0 + 8) * H_ + col) = v1;
            } else {
                int t0 = row0 >> 6, b0 = row0 & 63;
                int t1 = (row0 + 8) >> 6, b1 = (row0 + 8) & 63;
                *(float2*)(Cdst + ((size_t)b0 * T_ + t0) * O_ + col) = v0;
                *(float2*)(Cdst + ((size_t)b1 * T_ + t1) * O_ + col) = v1;
            }
        }
    }
}

__global__ __launch_bounds__(256, 2) void proj_tc(
    const float* __restrict__ bfv, const float* __restrict__ bbv)
{
    const int dir = blockIdx.z;
    gemm_mma_body<4, 0>(g_Xh, g_Xl,
                        g_pBh + dir * (H_ * E_), g_pBl + dir * (H_ * E_),
                        dir ? bbv : bfv,
                        dir ? g_xb : g_xf,
                        blockIdx.x * 128, blockIdx.y * 64, dir);
}

__global__ __launch_bounds__(256, 2) void out_tc(
    const float* __restrict__ byv, float* __restrict__ out)
{
    gemm_mma_body<8, 1>(g_hh, g_hl, g_oBh, g_oBl, byv, out,
                        blockIdx.x * 128, blockIdx.y * 64, 0);
}

// ---------------------------------------------------------------------------
// scan kernel — R8 winner + bf16 hi/lo h stores
// ---------------------------------------------------------------------------
extern __shared__ float smem_scan[];

__global__ __launch_bounds__(256) void scan_kernel(
    const float* __restrict__ Whh_f,
    const float* __restrict__ Whh_b,
    float* __restrict__ out)
{
    float*      h_sh = smem_scan;
    ulonglong2* Wsh2 = (ulonglong2*)(smem_scan + 2 * H_);

    const int t   = threadIdx.x;
    const int dir = blockIdx.x >> 6;
    const int b   = blockIdx.x & 63;

    const float* W    = dir ? Whh_b : Whh_f;
    const float* xarr = dir ? g_xb  : g_xf;

    u64 wreg[KREGP];
#pragma unroll
    for (int p = 0; p < KREGP; p++)
        wreg[p] = pk2(W[(size_t)(2 * p) * H_ + t], W[(size_t)(2 * p + 1) * H_ + t]);
    for (int r = 0; r < KSH2; r++) {
        ulonglong2 w;
        w.x = pk2(W[(size_t)(2 * KREGP + 4 * r + 0) * H_ + t], W[(size_t)(2 * KREGP + 4 * r + 1) * H_ + t]);
        w.y = pk2(W[(size_t)(2 * KREGP + 4 * r + 2) * H_ + t], W[(size_t)(2 * KREGP + 4 * r + 3) * H_ + t]);
        Wsh2[r * H_ + t] = w;
    }
    h_sh[t] = 0.f;
    __syncthreads();

    const float* xp = xarr + (size_t)b * H_ + t;

    // incremental bf16 h store pointers
    const size_t h0 = ((size_t)((dir ? (T_ - 1) : 0) * B_ + b)) * (2 * H_) + dir * H_ + t;
    __nv_bfloat16* ghh = g_hh + h0;
    __nv_bfloat16* ghl = g_hl + h0;
    const long long gstep = dir ? -(long long)(B_ * 2 * H_) : (long long)(B_ * 2 * H_);

    float xq[XPF];
#pragma unroll
    for (int i = 0; i < XPF; i++)
        xq[i] = (i < T_) ? xp[(size_t)i * (B_ * H_)] : 0.f;

    float hlast = 0.f;
    int p = 0;
    const u64 z2 = pk2(0.f, 0.f);

    for (int s = 0; s < T_; ++s) {
        u64 a0 = pk2(xq[0], 0.f), a1 = z2, a2 = z2, a3 = z2;
#pragma unroll
        for (int i = 0; i < XPF - 1; i++) xq[i] = xq[i + 1];
        if (s + XPF < T_) xq[XPF - 1] = xp[(size_t)(s + XPF) * (B_ * H_)];

        const ulonglong2* hc2 = (const ulonglong2*)(h_sh + p * H_);

#pragma unroll
        for (int q = 0; q < 2 * KREGP / 4; q++) {
            ulonglong2 hv = hc2[q];
            if (q & 1) {
                FMA2(a2, hv.x, wreg[2 * q + 0], a2);
                FMA2(a3, hv.y, wreg[2 * q + 1], a3);
            } else {
                FMA2(a0, hv.x, wreg[2 * q + 0], a0);
                FMA2(a1, hv.y, wreg[2 * q + 1], a1);
            }
        }
#pragma unroll
        for (int r = 0; r < KSH2; r++) {
            ulonglong2 hv = hc2[2 * KREGP / 4 + r];
            ulonglong2 wv = Wsh2[r * H_ + t];
            FMA2(a0, hv.x, wv.x, a0);
            FMA2(a1, hv.y, wv.y, a1);
        }

        float l0, u0, l1, u1, l2, u2, l3, u3;
        upk2(a0, l0, u0); upk2(a1, l1, u1);
        upk2(a2, l2, u2); upk2(a3, l3, u3);
        float sum = ((l0 + u0) + (l1 + u1)) + ((l2 + u2) + (l3 + u3));
        float hn = fast_tanh(sum);

        h_sh[(p ^ 1) * H_ + t] = hn;

        __nv_bfloat16 bh = __float2bfloat16_rn(hn);
        *ghh = bh;
        *ghl = __float2bfloat16_rn(hn - __bfloat162float(bh));
        ghh += gstep; ghl += gstep;

        hlast = hn;
        p ^= 1;
        __syncthreads();
    }

    out[(size_t)B_ * T_ * O_ + (size_t)dir * (B_ * H_) + (size_t)b * H_ + t] = hlast;
}

// ---------------------------------------------------------------------------
// launch
// ---------------------------------------------------------------------------
extern "C" void kernel_launch(void* const* d_in, const int* in_sizes, int n_in,
                              void* d_out, int out_size)
{
    const float* X    = (const float*)d_in[0];
    const float* Wxhf = (const float*)d_in[1];
    const float* Whhf = (const float*)d_in[2];
    const float* bf   = (const float*)d_in[3];
    const float* Wxhb = (const float*)d_in[4];
    const float* Whhb = (const float*)d_in[5];
    const float* bb   = (const float*)d_in[6];
    const float* Why  = (const float*)d_in[7];
    const float* by   = (const float*)d_in[8];
    float* out = (float*)d_out;

    cudaFuncSetAttribute(scan_kernel,
                         cudaFuncAttributeMaxDynamicSharedMemorySize, (int)SMEM_SCAN);
    cudaFuncSetAttribute(proj_tc,
                         cudaFuncAttributeMaxDynamicSharedMemorySize, (int)SMEM_TC);
    cudaFuncSetAttribute(out_tc,
                         cudaFuncAttributeMaxDynamicSharedMemorySize, (int)SMEM_TC);

    setup_kernel<<<256, 256>>>(Wxhf, Wxhb, Why);
    xcvt_kernel<<<1024, 256>>>(X);
    proj_tc<<<dim3(M_ / 128, H_ / 64, 2), 256, SMEM_TC>>>(bf, bb);
    scan_kernel<<<128, 256, SMEM_SCAN>>>(Whhf, Whhb, out);
    out_tc<<<dim3(M_ / 128, O_ / 64), 256, SMEM_TC>>>(by, out);
}

// round 15
// speedup vs baseline: 1.2163x; 1.2163x over previous
#include <cuda_runtime.h>
#include <cuda_bf16.h>
#include <math.h>
#include <stdint.h>

// Problem dims (fixed)
#define B_  64
#define T_  512
#define E_  256
#define H_  256
#define O_  256
#define M_  (T_ * B_)          // 32768 rows

typedef unsigned long long u64;
typedef unsigned int u32;

// ---------------------------------------------------------------------------
// scan config (R8/R12 winner)
// ---------------------------------------------------------------------------
#define KREGP 100
#define KSH2  14
#define SMEM_SCAN ((2 * H_) * sizeof(float) + (KSH2 * H_) * sizeof(ulonglong2))
#define XPF 4

__device__ __forceinline__ u64 pk2(float lo, float hi) {
    u64 r;
    asm("mov.b64 %0, {%1, %2};" : "=l"(r) : "f"(lo), "f"(hi));
    return r;
}
__device__ __forceinline__ void upk2(u64 v, float& lo, float& hi) {
    asm("mov.b64 {%0, %1}, %2;" : "=f"(lo), "=f"(hi) : "l"(v));
}
#define FMA2(d, a, b, c) \
    asm("fma.rn.f32x2 %0, %1, %2, %3;" : "=l"(d) : "l"(a), "l"(b), "l"(c))

__device__ __forceinline__ float fast_tanh(float v) {
    float x = fminf(fmaxf(v, -15.f), 15.f);
    float e = __expf(2.f * x);
    return __fdividef(e - 1.f, e + 1.f);
}

// ---------------------------------------------------------------------------
// warp-mma + cp.async helpers
// ---------------------------------------------------------------------------
__device__ __forceinline__ u32 smem_u32(const void* p) {
    u32 a;
    asm("{ .reg .u64 t; cvta.to.shared.u64 t, %1; cvt.u32.u64 %0, t; }" : "=r"(a) : "l"(p));
    return a;
}
#define LDSM_X4(r, addr) \
    asm volatile("ldmatrix.sync.aligned.m8n8.x4.shared.b16 {%0,%1,%2,%3}, [%4];" \
        : "=r"((r)[0]), "=r"((r)[1]), "=r"((r)[2]), "=r"((r)[3]) : "r"(addr))
#define MMA_BF16(c, a, b0, b1) \
    asm volatile("mma.sync.aligned.m16n8k16.row.col.f32.bf16.bf16.f32 " \
        "{%0,%1,%2,%3}, {%4,%5,%6,%7}, {%8,%9}, {%0,%1,%2,%3};" \
        : "+f"((c)[0]), "+f"((c)[1]), "+f"((c)[2]), "+f"((c)[3]) \
        : "r"((a)[0]), "r"((a)[1]), "r"((a)[2]), "r"((a)[3]), "r"(b0), "r"(b1))
#define CP16(dst, src) \
    asm volatile("cp.async.cg.shared.global [%0], [%1], 16;" :: "r"(dst), "l"(src))
#define CP_COMMIT()  asm volatile("cp.async.commit_group;" ::: "memory")
#define CP_WAIT1()   asm volatile("cp.async.wait_group 1;" ::: "memory")
#define CP_WAIT0()   asm volatile("cp.async.wait_group 0;" ::: "memory")

// ---------------------------------------------------------------------------
// Static device scratch
// ---------------------------------------------------------------------------
__device__ float g_xf[(size_t)T_ * B_ * H_];
__device__ float g_xb[(size_t)T_ * B_ * H_];
__device__ float g_h [(size_t)M_ * (2 * H_)];   // fp32 h history (scan output)

// X pre-converted to bf16 hi/lo (same [b][t][e] layout)
__device__ __nv_bfloat16 g_Xh[(size_t)B_ * T_ * E_];
__device__ __nv_bfloat16 g_Xl[(size_t)B_ * T_ * E_];

// weights pre-split bf16 hi/lo, TRANSPOSED to [n][k] (k contiguous)
__device__ __nv_bfloat16 g_pBh[2 * H_ * E_];
__device__ __nv_bfloat16 g_pBl[2 * H_ * E_];
__device__ __nv_bfloat16 g_oBh[O_ * 2 * H_];
__device__ __nv_bfloat16 g_oBl[O_ * 2 * H_];

// ---------------------------------------------------------------------------
// shared-memory layouts
// ---------------------------------------------------------------------------
#define ROWB 144
// proj (all-async) layout: A hi/lo double-buffered + B hi/lo double-buffered
#define ABUF 36864                    // per stage: AH +0 (18432), AL +18432
#define P_B0 (2 * ABUF)               // 73728
#define PBUF 18432                    // per stage: BH +0 (9216), BL +9216
#define SMEM_PROJ (P_B0 + 2 * PBUF)   // 110592
// out (cvt) layout: A hi/lo single + B hi/lo double-buffered
#define O_AH 0
#define O_AL 18432
#define O_B0 36864
#define OBUF 18432
#define SMEM_OUT (O_B0 + 2 * OBUF)    // 73728

__device__ __forceinline__ unsigned pkbf(float a, float b) {
    unsigned lo = __bfloat16_as_ushort(__float2bfloat16_rn(a));
    unsigned hi = __bfloat16_as_ushort(__float2bfloat16_rn(b));
    return (hi << 16) | lo;
}
__device__ __forceinline__ void cvt8(const float* v, uint4& Hq, uint4& Lq) {
    float fh[8], fl[8];
#pragma unroll
    for (int i = 0; i < 8; i++) {
        __nv_bfloat16 h = __float2bfloat16_rn(v[i]);
        fh[i] = __bfloat162float(h);
        fl[i] = v[i] - fh[i];
    }
    Hq.x = pkbf(fh[0], fh[1]); Hq.y = pkbf(fh[2], fh[3]);
    Hq.z = pkbf(fh[4], fh[5]); Hq.w = pkbf(fh[6], fh[7]);
    Lq.x = pkbf(fl[0], fl[1]); Lq.y = pkbf(fl[2], fl[3]);
    Lq.z = pkbf(fl[4], fl[5]); Lq.w = pkbf(fl[6], fl[7]);
}

// ---------------------------------------------------------------------------
// setup: split + transpose weights
// ---------------------------------------------------------------------------
__global__ void setup_kernel(const float* __restrict__ Wf,
                             const float* __restrict__ Wb,
                             const float* __restrict__ Why)
{
    const int stride = gridDim.x * blockDim.x;
    for (int e = blockIdx.x * blockDim.x + threadIdx.x; e < E_ * H_; e += stride) {
        int k = e >> 8, n = e & 255;
        int idx = n * E_ + k;
        float wf = Wf[e], wb = Wb[e];
        __nv_bfloat16 hf = __float2bfloat16_rn(wf);
        __nv_bfloat16 hb = __float2bfloat16_rn(wb);
        g_pBh[idx] = hf;
        g_pBl[idx] = __float2bfloat16_rn(wf - __bfloat162float(hf));
        g_pBh[H_ * E_ + idx] = hb;
        g_pBl[H_ * E_ + idx] = __float2bfloat16_rn(wb - __bfloat162float(hb));
    }
    for (int e = blockIdx.x * blockDim.x + threadIdx.x; e < 2 * H_ * O_; e += stride) {
        int k = e >> 8, n = e & 255;
        int idx = n * (2 * H_) + k;
        float w = Why[e];
        __nv_bfloat16 h = __float2bfloat16_rn(w);
        g_oBh[idx] = h;
        g_oBl[idx] = __float2bfloat16_rn(w - __bfloat162float(h));
    }
}

// convert X fp32 -> bf16 hi/lo (HBM-bound, ~11us)
__global__ void xcvt_kernel(const float* __restrict__ X)
{
    const size_t N = (size_t)B_ * T_ * E_;
    const size_t stride = (size_t)gridDim.x * blockDim.x;
    for (size_t i = (size_t)blockIdx.x * blockDim.x + threadIdx.x; i < N; i += stride) {
        float v = X[i];
        __nv_bfloat16 h = __float2bfloat16_rn(v);
        g_Xh[i] = h;
        g_Xl[i] = __float2bfloat16_rn(v - __bfloat162float(h));
    }
}

// ---------------------------------------------------------------------------
// proj GEMM (R13 body): A and B both streamed via cp.async, double-buffered.
// 128(M) x 64(N) tile, K = 256 (4 slabs). 8 warps as 4(M) x 2(N).
// ---------------------------------------------------------------------------
__global__ __launch_bounds__(256, 2) void proj_tc(
    const float* __restrict__ bfv, const float* __restrict__ bbv)
{
    extern __shared__ char smem[];
    const u32 smb = smem_u32(smem);
    const int dir = blockIdx.z;
    const int m0 = blockIdx.x * 128;
    const int n0 = blockIdx.y * 64;
    const __nv_bfloat16* Bh = g_pBh + dir * (H_ * E_);
    const __nv_bfloat16* Bl = g_pBl + dir * (H_ * E_);
    const float* bias = dir ? bbv : bfv;
    float* Cdst = dir ? g_xb : g_xf;
    const int NKT = 4, K = 256;

    const int tid = threadIdx.x;
    const int wid = tid >> 5;
    const int l   = tid & 31;
    const int wm  = wid & 3;
    const int wn  = wid >> 2;

    const int r  = tid >> 1;
    const int hf = tid & 1;
    size_t aoff;
    {
        const int m = m0 + r;
        int t = m >> 6, b = m & 63;
        int xt = dir ? (T_ - 1 - t) : t;
        aoff = ((size_t)b * T_ + xt) * E_ + hf * 32;
    }
    const u32 adst_off = (u32)(r * ROWB + hf * 64);

    const int slot  = tid >> 1;
    const int bhalf = tid & 1;
    const int barr  = slot >> 6;
    const int rb    = slot & 63;
    const __nv_bfloat16* bsrc = (barr ? Bl : Bh) + (size_t)(n0 + rb) * K + bhalf * 32;
    const u32 bdst_off = (u32)(P_B0 + barr * 9216 + rb * ROWB + bhalf * 64);

    u32 aOff[2];
#pragma unroll
    for (int f = 0; f < 2; f++)
        aOff[f] = (u32)((wm * 32 + 16 * f + (l & 15)) * ROWB + (l >> 4) * 16);
    u32 bOff[2];
#pragma unroll
    for (int p = 0; p < 2; p++)
        bOff[p] = (u32)((wn * 32 + 16 * p + (l & 7) + (l >> 4) * 8) * ROWB + ((l >> 3) & 1) * 16);

    float cc[2][4][4];
#pragma unroll
    for (int f = 0; f < 2; f++)
#pragma unroll
        for (int g = 0; g < 4; g++)
#pragma unroll
            for (int i = 0; i < 4; i++) cc[f][g][i] = 0.f;

#pragma unroll
    for (int i = 0; i < 4; i++) {
        CP16(smb + adst_off + i * 16,          (const char*)(g_Xh + aoff) + i * 16);
        CP16(smb + 18432 + adst_off + i * 16,  (const char*)(g_Xl + aoff) + i * 16);
        CP16(smb + bdst_off + i * 16,          (const char*)(bsrc) + i * 16);
    }
    CP_COMMIT();

    for (int kt = 0; kt < NKT; kt++) {
        const int buf = kt & 1;
        if (kt > 0) __syncthreads();

        if (kt + 1 < NKT) {
            const int nb = 1 - buf;
            const char* ah = (const char*)(g_Xh + aoff + (kt + 1) * 64);
            const char* al = (const char*)(g_Xl + aoff + (kt + 1) * 64);
            const char* bs = (const char*)(bsrc + (kt + 1) * 64);
#pragma unroll
            for (int i = 0; i < 4; i++) {
                CP16(smb + nb * ABUF + adst_off + i * 16,          ah + i * 16);
                CP16(smb + nb * ABUF + 18432 + adst_off + i * 16,  al + i * 16);
                CP16(smb + bdst_off + nb * PBUF + i * 16,          bs + i * 16);
            }
            CP_COMMIT();
            CP_WAIT1();
        } else {
            CP_WAIT0();
        }
        __syncthreads();

        const u32 ab = smb + buf * ABUF;
        const u32 bb = smb + buf * PBUF;
#pragma unroll
        for (int ks = 0; ks < 4; ks++) {
            const u32 kb = ks * 32;
            u32 ah2[2][4], al2[2][4], bh2[2][4], bl2[2][4];
#pragma unroll
            for (int f = 0; f < 2; f++) {
                LDSM_X4(ah2[f], ab + aOff[f] + kb);
                LDSM_X4(al2[f], ab + 18432 + aOff[f] + kb);
            }
#pragma unroll
            for (int p = 0; p < 2; p++) {
                LDSM_X4(bh2[p], bb + P_B0 + bOff[p] + kb);
                LDSM_X4(bl2[p], bb + P_B0 + 9216 + bOff[p] + kb);
            }
#pragma unroll
            for (int f = 0; f < 2; f++)
#pragma unroll
                for (int g = 0; g < 4; g++) {
                    u32 h0 = bh2[g >> 1][(g & 1) * 2], h1 = bh2[g >> 1][(g & 1) * 2 + 1];
                    u32 l0 = bl2[g >> 1][(g & 1) * 2], l1 = bl2[g >> 1][(g & 1) * 2 + 1];
                    MMA_BF16(cc[f][g], ah2[f], h0, h1);
                    MMA_BF16(cc[f][g], ah2[f], l0, l1);
                    MMA_BF16(cc[f][g], al2[f], h0, h1);
                }
        }
    }

#pragma unroll
    for (int f = 0; f < 2; f++) {
        const int row0 = m0 + wm * 32 + 16 * f + (l >> 2);
#pragma unroll
        for (int g = 0; g < 4; g++) {
            const int col = n0 + wn * 32 + 8 * g + (l & 3) * 2;
            float2 bv = *(const float2*)(bias + col);
            float2 v0 = { cc[f][g][0] + bv.x, cc[f][g][1] + bv.y };
            float2 v1 = { cc[f][g][2] + bv.x, cc[f][g][3] + bv.y };
            *(float2*)(Cdst + (size_t)row0 * H_ + col) = v0;
            *(float2*)(Cdst + (size_t)(row0 + 8) * H_ + col) = v1;
        }
    }
}

// ---------------------------------------------------------------------------
// out GEMM (R12 body, measured 141us): A fp32 from g_h with inline cvt,
// B via cp.async double-buffered. 128x64 tile, K = 512 (8 slabs).
// ---------------------------------------------------------------------------
__global__ __launch_bounds__(256, 2) void out_tc(
    const float* __restrict__ byv, float* __restrict__ out)
{
    extern __shared__ char smem[];
    const u32 smb = smem_u32(smem);
    const int m0 = blockIdx.x * 128;
    const int n0 = blockIdx.y * 64;
    const int NKT = 8, K = 512;

    const int tid = threadIdx.x;
    const int wid = tid >> 5;
    const int l   = tid & 31;
    const int wm  = wid & 3;
    const int wn  = wid >> 2;

    const int r  = tid >> 1;
    const int hf = tid & 1;
    const float* arow = g_h + (size_t)(m0 + r) * (2 * H_);

    const int slot  = tid >> 1;
    const int bhalf = tid & 1;
    const int barr  = slot >> 6;
    const int rb    = slot & 63;
    const __nv_bfloat16* bsrc = (barr ? g_oBl : g_oBh) + (size_t)(n0 + rb) * K + bhalf * 32;
    const u32 bdst_off = (u32)(O_B0 + barr * 9216 + rb * ROWB + bhalf * 64);

    u32 aAH[2], aAL[2];
#pragma unroll
    for (int f = 0; f < 2; f++) {
        u32 off = (u32)((wm * 32 + 16 * f + (l & 15)) * ROWB + (l >> 4) * 16);
        aAH[f] = smb + O_AH + off;
        aAL[f] = smb + O_AL + off;
    }
    u32 bOff[2];
#pragma unroll
    for (int p = 0; p < 2; p++)
        bOff[p] = (u32)((wn * 32 + 16 * p + (l & 7) + (l >> 4) * 8) * ROWB + ((l >> 3) & 1) * 16);

    float cc[2][4][4];
#pragma unroll
    for (int f = 0; f < 2; f++)
#pragma unroll
        for (int g = 0; g < 4; g++)
#pragma unroll
            for (int i = 0; i < 4; i++) cc[f][g][i] = 0.f;

    // prologue: B slab 0, A slab 0
#pragma unroll
    for (int i = 0; i < 4; i++)
        CP16(smb + bdst_off + i * 16, (const char*)(bsrc) + i * 16);
    CP_COMMIT();
    float av[32];
#pragma unroll
    for (int i = 0; i < 8; i++)
        *(float4*)&av[i * 4] = *(const float4*)(arow + hf * 32 + i * 4);

    for (int kt = 0; kt < NKT; kt++) {
        const int buf = kt & 1;
        if (kt > 0) __syncthreads();

        // store A (convert) into smem
#pragma unroll
        for (int c = 0; c < 4; c++) {
            uint4 Hq, Lq;
            cvt8(&av[c * 8], Hq, Lq);
            int off = r * ROWB + hf * 64 + c * 16;
            *(uint4*)(smem + O_AH + off) = Hq;
            *(uint4*)(smem + O_AL + off) = Lq;
        }

        if (kt + 1 < NKT) {
            const u32 nb = smb + bdst_off + (1 - buf) * OBUF;
            const char* ns = (const char*)(bsrc + (kt + 1) * 64);
#pragma unroll
            for (int i = 0; i < 4; i++) CP16(nb + i * 16, ns + i * 16);
            CP_COMMIT();
            CP_WAIT1();
        } else {
            CP_WAIT0();
        }
        __syncthreads();

        if (kt + 1 < NKT) {
            const float* ap = arow + (kt + 1) * 64 + hf * 32;
#pragma unroll
            for (int i = 0; i < 8; i++)
                *(float4*)&av[i * 4] = *(const float4*)(ap + i * 4);
        }

        const u32 bb = smb + buf * OBUF;
#pragma unroll
        for (int ks = 0; ks < 4; ks++) {
            const u32 kb = ks * 32;
            u32 ah2[2][4], al2[2][4], bh2[2][4], bl2[2][4];
#pragma unroll
            for (int f = 0; f < 2; f++) { LDSM_X4(ah2[f], aAH[f] + kb); LDSM_X4(al2[f], aAL[f] + kb); }
#pragma unroll
            for (int p = 0; p < 2; p++) {
                LDSM_X4(bh2[p], bb + O_B0 + bOff[p] + kb);
                LDSM_X4(bl2[p], bb + O_B0 + 9216 + bOff[p] + kb);
            }
#pragma unroll
            for (int f = 0; f < 2; f++)
#pragma unroll
                for (int g = 0; g < 4; g++) {
                    u32 h0 = bh2[g >> 1][(g & 1) * 2], h1 = bh2[g >> 1][(g & 1) * 2 + 1];
                    u32 l0 = bl2[g >> 1][(g & 1) * 2], l1 = bl2[g >> 1][(g & 1) * 2 + 1];
                    MMA_BF16(cc[f][g], ah2[f], h0, h1);
                    MMA_BF16(cc[f][g], ah2[f], l0, l1);
                    MMA_BF16(cc[f][g], al2[f], h0, h1);
                }
        }
    }

#pragma unroll
    for (int f = 0; f < 2; f++) {
        const int row0 = m0 + wm * 32 + 16 * f + (l >> 2);
#pragma unroll
        for (int g = 0; g < 4; g++) {
            const int col = n0 + wn * 32 + 8 * g + (l & 3) * 2;
            float2 bv = *(const float2*)(byv + col);
            float2 v0 = { cc[f][g][0] + bv.x, cc[f][g][1] + bv.y };
            float2 v1 = { cc[f][g][2] + bv.x, cc[f][g][3] + bv.y };
            int t0 = row0 >> 6, b0 = row0 & 63;
            int t1 = (row0 + 8) >> 6, b1 = (row0 + 8) & 63;
            *(float2*)(out + ((size_t)b0 * T_ + t0) * O_ + col) = v0;
            *(float2*)(out + ((size_t)b1 * T_ + t1) * O_ + col) = v1;
        }
    }
}

// ---------------------------------------------------------------------------
// scan kernel — EXACT R12 winner (fp32 g_h store, no conversions)
// ---------------------------------------------------------------------------
extern __shared__ float smem_scan[];

__global__ __launch_bounds__(256) void scan_kernel(
    const float* __restrict__ Whh_f,
    const float* __restrict__ Whh_b,
    float* __restrict__ out)
{
    float*      h_sh = smem_scan;
    ulonglong2* Wsh2 = (ulonglong2*)(smem_scan + 2 * H_);

    const int t   = threadIdx.x;
    const int dir = blockIdx.x >> 6;
    const int b   = blockIdx.x & 63;

    const float* W    = dir ? Whh_b : Whh_f;
    const float* xarr = dir ? g_xb  : g_xf;

    u64 wreg[KREGP];
#pragma unroll
    for (int p = 0; p < KREGP; p++)
        wreg[p] = pk2(W[(size_t)(2 * p) * H_ + t], W[(size_t)(2 * p + 1) * H_ + t]);
    for (int r = 0; r < KSH2; r++) {
        ulonglong2 w;
        w.x = pk2(W[(size_t)(2 * KREGP + 4 * r + 0) * H_ + t], W[(size_t)(2 * KREGP + 4 * r + 1) * H_ + t]);
        w.y = pk2(W[(size_t)(2 * KREGP + 4 * r + 2) * H_ + t], W[(size_t)(2 * KREGP + 4 * r + 3) * H_ + t]);
        Wsh2[r * H_ + t] = w;
    }
    h_sh[t] = 0.f;
    __syncthreads();

    const float* xp = xarr + (size_t)b * H_ + t;

    float* ghp = g_h + ((size_t)((dir ? (T_ - 1) : 0) * B_ + b)) * (2 * H_) + dir * H_ + t;
    const long long gstep = dir ? -(long long)(B_ * 2 * H_) : (long long)(B_ * 2 * H_);

    float xq[XPF];
#pragma unroll
    for (int i = 0; i < XPF; i++)
        xq[i] = (i < T_) ? xp[(size_t)i * (B_ * H_)] : 0.f;

    float hlast = 0.f;
    int p = 0;
    const u64 z2 = pk2(0.f, 0.f);

    for (int s = 0; s < T_; ++s) {
        u64 a0 = pk2(xq[0], 0.f), a1 = z2, a2 = z2, a3 = z2;
#pragma unroll
        for (int i = 0; i < XPF - 1; i++) xq[i] = xq[i + 1];
        if (s + XPF < T_) xq[XPF - 1] = xp[(size_t)(s + XPF) * (B_ * H_)];

        const ulonglong2* hc2 = (const ulonglong2*)(h_sh + p * H_);

#pragma unroll
        for (int q = 0; q < 2 * KREGP / 4; q++) {
            ulonglong2 hv = hc2[q];
            if (q & 1) {
                FMA2(a2, hv.x, wreg[2 * q + 0], a2);
                FMA2(a3, hv.y, wreg[2 * q + 1], a3);
            } else {
                FMA2(a0, hv.x, wreg[2 * q + 0], a0);
                FMA2(a1, hv.y, wreg[2 * q + 1], a1);
            }
        }
#pragma unroll
        for (int r = 0; r < KSH2; r++) {
            ulonglong2 hv = hc2[2 * KREGP / 4 + r];
            ulonglong2 wv = Wsh2[r * H_ + t];
            FMA2(a0, hv.x, wv.x, a0);
            FMA2(a1, hv.y, wv.y, a1);
        }

        float l0, u0, l1, u1, l2, u2, l3, u3;
        upk2(a0, l0, u0); upk2(a1, l1, u1);
        upk2(a2, l2, u2); upk2(a3, l3, u3);
        float sum = ((l0 + u0) + (l1 + u1)) + ((l2 + u2) + (l3 + u3));
        float hn = fast_tanh(sum);

        h_sh[(p ^ 1) * H_ + t] = hn;
        *ghp = hn;
        ghp += gstep;

        hlast = hn;
        p ^= 1;
        __syncthreads();
    }

    out[(size_t)B_ * T_ * O_ + (size_t)dir * (B_ * H_) + (size_t)b * H_ + t] = hlast;
}

// ---------------------------------------------------------------------------
// launch
// ---------------------------------------------------------------------------
extern "C" void kernel_launch(void* const* d_in, const int* in_sizes, int n_in,
                              void* d_out, int out_size)
{
    const float* X    = (const float*)d_in[0];
    const float* Wxhf = (const float*)d_in[1];
    const float* Whhf = (const float*)d_in[2];
    const float* bf   = (const float*)d_in[3];
    const float* Wxhb = (const float*)d_in[4];
    const float* Whhb = (const float*)d_in[5];
    const float* bb   = (const float*)d_in[6];
    const float* Why  = (const float*)d_in[7];
    const float* by   = (const float*)d_in[8];
    float* out = (float*)d_out;

    cudaFuncSetAttribute(scan_kernel,
                         cudaFuncAttributeMaxDynamicSharedMemorySize, (int)SMEM_SCAN);
    cudaFuncSetAttribute(proj_tc,
                         cudaFuncAttributeMaxDynamicSharedMemorySize, (int)SMEM_PROJ);
    cudaFuncSetAttribute(out_tc,
                         cudaFuncAttributeMaxDynamicSharedMemorySize, (int)SMEM_OUT);

    setup_kernel<<<256, 256>>>(Wxhf, Wxhb, Why);
    xcvt_kernel<<<1024, 256>>>(X);
    proj_tc<<<dim3(M_ / 128, H_ / 64, 2), 256, SMEM_PROJ>>>(bf, bb);
    scan_kernel<<<128, 256, SMEM_SCAN>>>(Whhf, Whhb, out);
    out_tc<<<dim3(M_ / 128, O_ / 64), 256, SMEM_OUT>>>(by, out);
}